// round 7
// baseline (speedup 1.0000x reference)
#include <cuda_runtime.h>
#include <cstdint>

#define TSTEPS 2048
#define BATCH  32
#define EDIM   512
#define HDIM   512
#define C4     2048
#define NCTA   128

__device__ float    g_xp[(size_t)TSTEPS * C4 * BATCH];   // [t][c][b]
__device__ float    g_h[2][HDIM * BATCH];                // ull idx k2*32+b = (h[2k2][b], h[2k2+1][b])
__device__ unsigned g_bar;

__device__ __forceinline__ unsigned long long ffma2(unsigned long long a,
                                                    unsigned long long b,
                                                    unsigned long long c) {
    unsigned long long d;
    asm("fma.rn.f32x2 %0, %1, %2, %3;" : "=l"(d) : "l"(a), "l"(b), "l"(c));
    return d;
}

__device__ __forceinline__ unsigned long long fadd2(unsigned long long a,
                                                    unsigned long long b) {
    unsigned long long d;
    asm("add.rn.f32x2 %0, %1, %2;" : "=l"(d) : "l"(a), "l"(b));
    return d;
}

__device__ __forceinline__ float hsum2(unsigned long long u) {
    return __uint_as_float((unsigned)u) + __uint_as_float((unsigned)(u >> 32));
}

__device__ __forceinline__ float sigf(float x) { return 1.0f / (1.0f + __expf(-x)); }

// tanh(x) = 2*sigmoid(2x) - 1, MUFU-based. |err| ~1e-6 abs, fine for 1e-3 budget.
__device__ __forceinline__ float tanhf_fast(float x) {
    return __fmaf_rn(2.0f, sigf(2.0f * x), -1.0f);
}

__device__ __forceinline__ unsigned long long pack2(float lo, float hi) {
    return ((unsigned long long)__float_as_uint(hi) << 32) |
           (unsigned long long)__float_as_uint(lo);
}

// ---------------------------------------------------------------------------
__global__ void k_init() {
    int i = blockIdx.x * blockDim.x + threadIdx.x;
    if (i < 2 * HDIM * BATCH) ((float*)g_h)[i] = 0.0f;
    if (i == 0) g_bar = 0u;
}

// ---------------------------------------------------------------------------
// Phase 1 (unchanged from R4 pass): xp[t][c][b] = embeds[t][b][:]@Wx[:,c]+b[c]
// ---------------------------------------------------------------------------
__global__ void __launch_bounds__(256, 2) k_xproj(
    const float* __restrict__ emb,
    const float* __restrict__ wxi, const float* __restrict__ wxf,
    const float* __restrict__ wxg, const float* __restrict__ wxo,
    const float* __restrict__ bi,  const float* __restrict__ bf,
    const float* __restrict__ bg,  const float* __restrict__ bo)
{
    extern __shared__ float sm[];
    float2*             a2 = (float2*)sm;                        // [256 k2][32 b] swizzled
    unsigned long long* w2 = (unsigned long long*)(sm + 16384);  // 2 bufs x 2048 ull

    const int tid  = threadIdx.x;
    const int lane = tid & 31;
    const int wrp  = tid >> 5;
    const int t    = blockIdx.y;
    const int ct   = blockIdx.x;
    const int gate = ct >> 2;
    const int co   = (ct & 3) * 128;

    const float* W  = (gate == 0) ? wxi : (gate == 1) ? wxf : (gate == 2) ? wxg : wxo;
    const float* bs = (gate == 0) ? bi  : (gate == 1) ? bf  : (gate == 2) ? bg  : bo;

    {
        const float2* src = (const float2*)(emb + (size_t)t * (BATCH * EDIM));
        const int k2 = tid, sw = k2 & 31;
        #pragma unroll
        for (int b = 0; b < 32; b++)
            a2[k2 * 32 + (b ^ sw)] = src[b * 256 + k2];
    }

    float4 r0[2], r1[2];
    #pragma unroll
    for (int i = 0; i < 2; i++) {
        int k2l = wrp * 2 + i;
        const float* Wp = &W[(size_t)(k2l * 2) * HDIM + co + lane * 4];
        r0[i] = *(const float4*)Wp;
        r1[i] = *(const float4*)(Wp + HDIM);
    }
    {
        const int sxor = (lane & 7) << 1;
        #pragma unroll
        for (int i = 0; i < 2; i++) {
            int k2l = wrp * 2 + i;
            int s = k2l ^ sxor;
            float v0[4] = {r0[i].x, r0[i].y, r0[i].z, r0[i].w};
            float v1[4] = {r1[i].x, r1[i].y, r1[i].z, r1[i].w};
            #pragma unroll
            for (int j = 0; j < 4; j++)
                w2[(lane * 4 + j) * 16 + s] = pack2(v0[j], v1[j]);
        }
    }
    __syncthreads();

    unsigned long long acc[16];
    #pragma unroll
    for (int j = 0; j < 16; j++) acc[j] = 0ull;

    const unsigned long long* a2u = (const unsigned long long*)a2;
    int p = 0;
    for (int kc = 0; kc < 16; kc++) {
        if (kc < 15) {
            #pragma unroll
            for (int i = 0; i < 2; i++) {
                int k2l = wrp * 2 + i;
                const float* Wp = &W[(size_t)((kc + 1) * 32 + k2l * 2) * HDIM + co + lane * 4];
                r0[i] = *(const float4*)Wp;
                r1[i] = *(const float4*)(Wp + HDIM);
            }
        }
        const unsigned long long* wu = w2 + p * 2048;
        const int k2g0 = kc * 16;
        #pragma unroll
        for (int k2l = 0; k2l < 16; k2l += 2) {
            int kA = k2g0 + k2l, kB = kA + 1;
            unsigned long long h0 = a2u[kA * 32 + (lane ^ (kA & 31))];
            unsigned long long h1 = a2u[kB * 32 + (lane ^ (kB & 31))];
            #pragma unroll
            for (int j = 0; j < 16; j++) {
                int c = wrp * 16 + j;
                int s = k2l ^ (((c >> 2) & 7) << 1);
                ulonglong2 wv = *(const ulonglong2*)&wu[c * 16 + s];
                acc[j] = ffma2(h0, wv.x, acc[j]);
                acc[j] = ffma2(h1, wv.y, acc[j]);
            }
        }
        if (kc < 15) {
            unsigned long long* wdst = w2 + (p ^ 1) * 2048;
            const int sxor = (lane & 7) << 1;
            #pragma unroll
            for (int i = 0; i < 2; i++) {
                int k2l = wrp * 2 + i;
                int s = k2l ^ sxor;
                float v0[4] = {r0[i].x, r0[i].y, r0[i].z, r0[i].w};
                float v1[4] = {r1[i].x, r1[i].y, r1[i].z, r1[i].w};
                #pragma unroll
                for (int j = 0; j < 4; j++)
                    wdst[(lane * 4 + j) * 16 + s] = pack2(v0[j], v1[j]);
            }
        }
        __syncthreads();
        p ^= 1;
    }

    float* xp = g_xp + ((size_t)t * C4 + (size_t)gate * 512 + co) * 32;
    #pragma unroll
    for (int j = 0; j < 16; j++) {
        int c = wrp * 16 + j;
        float s = hsum2(acc[j]) + __ldg(&bs[co + c]);
        xp[(size_t)c * 32 + lane] = s;
    }
}

// ---------------------------------------------------------------------------
// Phase 2: persistent recurrence, 128 CTAs x 512 threads (4 warps/SMSP).
// Warp w owns k2-slice [w*16, w*16+16); 16 gate-cols per CTA; h LDGs
// front-batched; packed-f32x2 reduction; coalesced out via smem transpose.
// SMEM: whs 32KB | outstage 512B+pad | red 64KB (ull partials).
// ---------------------------------------------------------------------------
__global__ void __launch_bounds__(512, 1) k_rec(
    const float* __restrict__ whi, const float* __restrict__ whf,
    const float* __restrict__ whg, const float* __restrict__ who,
    float* __restrict__ out)
{
    extern __shared__ float smr[];
    float2*             whs = (float2*)smr;                             // [16 lc][256 k2]
    float*              ost = smr + 8192;                               // [32 b][4 hu]
    unsigned long long* red = (unsigned long long*)(smr + 8320);        // [16 w][16 lc][32 b]

    const int tid  = threadIdx.x;
    const int lane = tid & 31;
    const int wrp  = tid >> 5;       // 0..15
    const int cta  = blockIdx.x;

    // Stage Wh slice (one-time): lc = gate*4+hu, col = cta*4+hu.
    for (int i = tid; i < 16 * 256; i += 512) {
        int lc = i >> 8, k2 = i & 255;
        int gate = lc >> 2, hu = lc & 3;
        const float* Wp = (gate == 0) ? whi : (gate == 1) ? whf : (gate == 2) ? whg : who;
        int col = cta * 4 + hu;
        whs[i] = make_float2(Wp[(size_t)(2 * k2) * HDIM + col],
                             Wp[(size_t)(2 * k2 + 1) * HDIM + col]);
    }
    __syncthreads();

    const int b_g  = tid & 31;       // gate-phase batch (tid<128)
    const int hu_g = tid >> 5;       // gate-phase h-unit (tid<128)
    float c_state = 0.0f;

    const int k2base = wrp * 16;
    volatile unsigned* vbar = &g_bar;

    for (int t = 0; t < TSTEPS; t++) {
        const int pin = t & 1;
        const unsigned long long* hin = (const unsigned long long*)g_h[pin];

        // Front-batch all 16 h loads for this warp's k2-slice (MLP 16).
        unsigned long long hreg[16];
        #pragma unroll
        for (int i = 0; i < 16; i++)
            hreg[i] = __ldcg(&hin[(k2base + i) * 32 + lane]);

        // xp prefetch for gate threads (consumed ~2K cycles later).
        float xpv[4];
        if (tid < 128) {
            #pragma unroll
            for (int g = 0; g < 4; g++) {
                size_t xpi = ((size_t)t * C4 + (size_t)(g * 512 + cta * 4 + hu_g)) * 32 + b_g;
                xpv[g] = __ldcg(&g_xp[xpi]);
            }
        }

        unsigned long long acc[16];
        #pragma unroll
        for (int lc = 0; lc < 16; lc++) acc[lc] = 0ull;

        const unsigned long long* whu = (const unsigned long long*)whs;
        #pragma unroll
        for (int k2l = 0; k2l < 16; k2l += 2) {
            int k2 = k2base + k2l;
            #pragma unroll
            for (int lc = 0; lc < 16; lc++) {
                ulonglong2 wv = *(const ulonglong2*)&whu[lc * 256 + k2];
                acc[lc] = ffma2(hreg[k2l],     wv.x, acc[lc]);
                acc[lc] = ffma2(hreg[k2l + 1], wv.y, acc[lc]);
            }
        }

        // Raw packed partials to smem (no horizontal sum here).
        #pragma unroll
        for (int lc = 0; lc < 16; lc++)
            red[(wrp * 16 + lc) * 32 + lane] = acc[lc];
        __syncthreads();

        float hval = 0.0f;
        if (tid < 128) {
            float s[4];
            #pragma unroll
            for (int g = 0; g < 4; g++) {
                int lc = g * 4 + hu_g;
                unsigned long long v[16];
                #pragma unroll
                for (int w = 0; w < 16; w++) v[w] = red[(w * 16 + lc) * 32 + b_g];
                #pragma unroll
                for (int st = 8; st >= 1; st >>= 1)
                    #pragma unroll
                    for (int w = 0; w < st; w++) v[w] = fadd2(v[w], v[w + st]);
                s[g] = hsum2(v[0]) + xpv[g];
            }
            float ig = sigf(s[0]);
            float fg = sigf(s[1]);
            float gg = tanhf_fast(s[2]);
            float og = sigf(s[3]);
            c_state = fg * c_state + ig * gg;
            hval = og * tanhf_fast(c_state);

            int col = cta * 4 + hu_g;
            float* hout = (float*)g_h[pin ^ 1];
            __stcg(&hout[(col >> 1) * 64 + b_g * 2 + (col & 1)], hval);
            ost[b_g * 4 + hu_g] = hval;
            __threadfence();                 // h visible gpu-wide before arrive
        }
        __syncthreads();                     // red consumed + h/ost stores done

        if (tid == 0) atomicAdd(&g_bar, 1u); // arrive early...

        // ...then do the out store while other CTAs straggle in.
        if (tid < 32) {
            float4 o4 = *(const float4*)&ost[tid * 4];
            *(float4*)&out[(size_t)t * (BATCH * HDIM) + (size_t)tid * HDIM + cta * 4] = o4;
        }

        if (t < TSTEPS - 1) {
            if (tid == 0) {
                unsigned target = (unsigned)NCTA * (unsigned)(t + 1);
                while (*vbar < target) { }
                __threadfence();
            }
            __syncthreads();
        }
    }
}

// ---------------------------------------------------------------------------
extern "C" void kernel_launch(void* const* d_in, const int* in_sizes, int n_in,
                              void* d_out, int out_size) {
    const float* emb = (const float*)d_in[0];
    const float* wxi = (const float*)d_in[1];
    const float* whi = (const float*)d_in[2];
    const float* bi  = (const float*)d_in[3];
    const float* wxf = (const float*)d_in[4];
    const float* whf = (const float*)d_in[5];
    const float* bf  = (const float*)d_in[6];
    const float* wxg = (const float*)d_in[7];
    const float* whg = (const float*)d_in[8];
    const float* bg  = (const float*)d_in[9];
    const float* wxo = (const float*)d_in[10];
    const float* who = (const float*)d_in[11];
    const float* bo  = (const float*)d_in[12];
    float* out = (float*)d_out;

    cudaFuncSetAttribute(k_xproj, cudaFuncAttributeMaxDynamicSharedMemorySize, 98304);
    cudaFuncSetAttribute(k_rec,   cudaFuncAttributeMaxDynamicSharedMemorySize, 102400);

    k_xproj<<<dim3(16, TSTEPS), 256, 98304>>>(emb, wxi, wxf, wxg, wxo, bi, bf, bg, bo);
    k_init<<<128, 256>>>();
    // smem: whs 32768 + ost 512 + red 65536 (at float offset 8320) = 99072 B
    k_rec<<<NCTA, 512, 99072>>>(whi, whf, whg, who, out);
}

// round 8
// speedup vs baseline: 1.1020x; 1.1020x over previous
#include <cuda_runtime.h>
#include <cstdint>

#define TSTEPS 2048
#define BATCH  32
#define EDIM   512
#define HDIM   512
#define C4     2048
#define NCTA   128

__device__ float    g_xp[(size_t)TSTEPS * C4 * BATCH];   // [t][c][b]
__device__ float    g_h[2][HDIM * BATCH];                // ull idx k2*32+b = (h[2k2][b], h[2k2+1][b])
__device__ unsigned g_grp[8];                            // tree barrier: 16 CTAs per group
__device__ unsigned g_root;

__device__ __forceinline__ unsigned long long ffma2(unsigned long long a,
                                                    unsigned long long b,
                                                    unsigned long long c) {
    unsigned long long d;
    asm("fma.rn.f32x2 %0, %1, %2, %3;" : "=l"(d) : "l"(a), "l"(b), "l"(c));
    return d;
}

__device__ __forceinline__ unsigned long long fadd2(unsigned long long a,
                                                    unsigned long long b) {
    unsigned long long d;
    asm("add.rn.f32x2 %0, %1, %2;" : "=l"(d) : "l"(a), "l"(b));
    return d;
}

__device__ __forceinline__ float hsum2(unsigned long long u) {
    return __uint_as_float((unsigned)u) + __uint_as_float((unsigned)(u >> 32));
}

__device__ __forceinline__ float sigf(float x) { return 1.0f / (1.0f + __expf(-x)); }

__device__ __forceinline__ float tanhf_fast(float x) {
    return __fmaf_rn(2.0f, sigf(2.0f * x), -1.0f);
}

__device__ __forceinline__ unsigned long long pack2(float lo, float hi) {
    return ((unsigned long long)__float_as_uint(hi) << 32) |
           (unsigned long long)__float_as_uint(lo);
}

// ---------------------------------------------------------------------------
__global__ void k_init() {
    int i = blockIdx.x * blockDim.x + threadIdx.x;
    if (i < 2 * HDIM * BATCH) ((float*)g_h)[i] = 0.0f;
    if (i < 8) g_grp[i] = 0u;
    if (i == 8) g_root = 0u;
}

// ---------------------------------------------------------------------------
// Phase 1: xp[t][c][b] = embeds[t][b][:]@Wx[:,c]+b[c]
// A resident swizzled (64KB); W streamed in 16 double-buffered 32-k chunks,
// layout [k2][c] (k-parity packed): staging 2xSTS.128 (2-way conflict),
// compute reads broadcast ulonglong2 -> no XOR math in the hot loop.
// ---------------------------------------------------------------------------
__global__ void __launch_bounds__(256, 2) k_xproj(
    const float* __restrict__ emb,
    const float* __restrict__ wxi, const float* __restrict__ wxf,
    const float* __restrict__ wxg, const float* __restrict__ wxo,
    const float* __restrict__ bi,  const float* __restrict__ bf,
    const float* __restrict__ bg,  const float* __restrict__ bo)
{
    extern __shared__ float sm[];
    float2*             a2 = (float2*)sm;                        // [256 k2][32 b] swizzled
    unsigned long long* w2 = (unsigned long long*)(sm + 16384);  // 2 bufs x [16 k2][128 c]

    const int tid  = threadIdx.x;
    const int lane = tid & 31;
    const int wrp  = tid >> 5;
    const int t    = blockIdx.y;
    const int ct   = blockIdx.x;
    const int gate = ct >> 2;
    const int co   = (ct & 3) * 128;

    const float* W  = (gate == 0) ? wxi : (gate == 1) ? wxf : (gate == 2) ? wxg : wxo;
    const float* bs = (gate == 0) ? bi  : (gate == 1) ? bf  : (gate == 2) ? bg  : bo;

    // Stage A: thread owns k2 = tid for all 32 b (coalesced LDG.64 per b).
    {
        const float2* src = (const float2*)(emb + (size_t)t * (BATCH * EDIM));
        const int k2 = tid, sw = k2 & 31;
        #pragma unroll
        for (int b = 0; b < 32; b++)
            a2[k2 * 32 + (b ^ sw)] = src[b * 256 + k2];
    }

    // W staging: thread (wrp,lane), i in {0,1}: k2l = wrp*2+i, cols co+lane*4..+3.
    float4 r0[2], r1[2];
    #pragma unroll
    for (int i = 0; i < 2; i++) {
        int k2l = wrp * 2 + i;
        const float* Wp = &W[(size_t)(k2l * 2) * HDIM + co + lane * 4];
        r0[i] = *(const float4*)Wp;
        r1[i] = *(const float4*)(Wp + HDIM);
    }
    #pragma unroll
    for (int i = 0; i < 2; i++) {
        int k2l = wrp * 2 + i;
        ulonglong2* dst = (ulonglong2*)&w2[k2l * 128 + lane * 4];
        dst[0] = make_ulonglong2(pack2(r0[i].x, r1[i].x), pack2(r0[i].y, r1[i].y));
        dst[1] = make_ulonglong2(pack2(r0[i].z, r1[i].z), pack2(r0[i].w, r1[i].w));
    }
    __syncthreads();

    unsigned long long acc[16];
    #pragma unroll
    for (int j = 0; j < 16; j++) acc[j] = 0ull;

    const unsigned long long* a2u = (const unsigned long long*)a2;
    int p = 0;
    for (int kc = 0; kc < 16; kc++) {
        if (kc < 15) {
            #pragma unroll
            for (int i = 0; i < 2; i++) {
                int k2l = wrp * 2 + i;
                const float* Wp = &W[(size_t)((kc + 1) * 32 + k2l * 2) * HDIM + co + lane * 4];
                r0[i] = *(const float4*)Wp;
                r1[i] = *(const float4*)(Wp + HDIM);
            }
        }
        const unsigned long long* wu = w2 + p * 2048;
        const int k2g0 = kc * 16;
        #pragma unroll
        for (int k2l = 0; k2l < 16; k2l++) {
            int kA = k2g0 + k2l;
            unsigned long long h0 = a2u[kA * 32 + (lane ^ (kA & 31))];
            #pragma unroll
            for (int jj = 0; jj < 16; jj += 2) {
                ulonglong2 wv = *(const ulonglong2*)&wu[k2l * 128 + wrp * 16 + jj];
                acc[jj]     = ffma2(h0, wv.x, acc[jj]);
                acc[jj + 1] = ffma2(h0, wv.y, acc[jj + 1]);
            }
        }
        if (kc < 15) {
            unsigned long long* wd = w2 + (p ^ 1) * 2048;
            #pragma unroll
            for (int i = 0; i < 2; i++) {
                int k2l = wrp * 2 + i;
                ulonglong2* dst = (ulonglong2*)&wd[k2l * 128 + lane * 4];
                dst[0] = make_ulonglong2(pack2(r0[i].x, r1[i].x), pack2(r0[i].y, r1[i].y));
                dst[1] = make_ulonglong2(pack2(r0[i].z, r1[i].z), pack2(r0[i].w, r1[i].w));
            }
        }
        __syncthreads();
        p ^= 1;
    }

    float* xp = g_xp + ((size_t)t * C4 + (size_t)gate * 512 + co) * 32;
    #pragma unroll
    for (int j = 0; j < 16; j++) {
        int c = wrp * 16 + j;
        float s = hsum2(acc[j]) + __ldg(&bs[co + c]);
        xp[(size_t)c * 32 + lane] = s;
    }
}

// ---------------------------------------------------------------------------
// Phase 2: persistent recurrence, 128 CTAs x 512 threads.
// Tree barrier (8 groups x 16 CTAs) with acq_rel/release atomics + acquire
// polls; NO threadfence. Reduce parallelized across all 512 threads.
// ---------------------------------------------------------------------------
__global__ void __launch_bounds__(512, 1) k_rec(
    const float* __restrict__ whi, const float* __restrict__ whf,
    const float* __restrict__ whg, const float* __restrict__ who,
    float* __restrict__ out)
{
    extern __shared__ float smr[];
    float2*             whs   = (float2*)smr;                         // [16 lc][256 k2]
    float*              ost   = smr + 8192;                           // [32 b][4 hu]
    float*              sgate = smr + 8320;                           // [16 lc][32 b]
    unsigned long long* red   = (unsigned long long*)(smr + 8832);    // [16 w][16 lc][32 b]

    const int tid  = threadIdx.x;
    const int lane = tid & 31;
    const int wrp  = tid >> 5;       // 0..15
    const int cta  = blockIdx.x;

    // Stage Wh slice (one-time): lc = gate*4+hu, col = cta*4+hu.
    for (int i = tid; i < 16 * 256; i += 512) {
        int lc = i >> 8, k2 = i & 255;
        int gate = lc >> 2, hu = lc & 3;
        const float* Wp = (gate == 0) ? whi : (gate == 1) ? whf : (gate == 2) ? whg : who;
        int col = cta * 4 + hu;
        whs[i] = make_float2(Wp[(size_t)(2 * k2) * HDIM + col],
                             Wp[(size_t)(2 * k2 + 1) * HDIM + col]);
    }
    __syncthreads();

    // Reduce-phase mapping: thread -> (lc_r, b_r). Gate-phase: tid<128 -> (hu_g, b_g).
    const int lc_r = tid >> 5;
    const int b_r  = tid & 31;
    const int b_g  = tid & 31;
    const int hu_g = tid >> 5;
    float c_state = 0.0f;

    const int k2base = wrp * 16;
    unsigned* grpp  = &g_grp[cta >> 4];
    unsigned* rootp = &g_root;

    for (int t = 0; t < TSTEPS; t++) {
        const int pin = t & 1;
        const unsigned long long* hin = (const unsigned long long*)g_h[pin];

        // Front-batch h loads (MLP 16) + this thread's xp element.
        unsigned long long hreg[16];
        #pragma unroll
        for (int i = 0; i < 16; i++)
            hreg[i] = __ldcg(&hin[(k2base + i) * 32 + lane]);
        float xpv;
        {
            int gate = lc_r >> 2, hu = lc_r & 3;
            xpv = __ldcg(&g_xp[((size_t)t * C4 + (size_t)(gate * 512 + cta * 4 + hu)) * 32 + b_r]);
        }

        unsigned long long acc[16];
        #pragma unroll
        for (int lc = 0; lc < 16; lc++) acc[lc] = 0ull;

        const unsigned long long* whu = (const unsigned long long*)whs;
        #pragma unroll
        for (int k2l = 0; k2l < 16; k2l += 2) {
            int k2 = k2base + k2l;
            #pragma unroll
            for (int lc = 0; lc < 16; lc++) {
                ulonglong2 wv = *(const ulonglong2*)&whu[lc * 256 + k2];
                acc[lc] = ffma2(hreg[k2l],     wv.x, acc[lc]);
                acc[lc] = ffma2(hreg[k2l + 1], wv.y, acc[lc]);
            }
        }

        #pragma unroll
        for (int lc = 0; lc < 16; lc++)
            red[(wrp * 16 + lc) * 32 + lane] = acc[lc];
        __syncthreads();

        // Parallel reduce: every thread owns one (lc, b).
        {
            unsigned long long v[16];
            #pragma unroll
            for (int w = 0; w < 16; w++) v[w] = red[(w * 16 + lc_r) * 32 + b_r];
            #pragma unroll
            for (int st = 8; st >= 1; st >>= 1)
                #pragma unroll
                for (int w = 0; w < st; w++) v[w] = fadd2(v[w], v[w + st]);
            sgate[lc_r * 32 + b_r] = hsum2(v[0]) + xpv;
        }
        __syncthreads();

        if (tid < 128) {
            float s0 = sgate[(0 * 4 + hu_g) * 32 + b_g];
            float s1 = sgate[(1 * 4 + hu_g) * 32 + b_g];
            float s2 = sgate[(2 * 4 + hu_g) * 32 + b_g];
            float s3 = sgate[(3 * 4 + hu_g) * 32 + b_g];
            float ig = sigf(s0);
            float fg = sigf(s1);
            float gg = tanhf_fast(s2);
            float og = sigf(s3);
            c_state = fg * c_state + ig * gg;
            float hval = og * tanhf_fast(c_state);

            int col = cta * 4 + hu_g;
            float* hout = (float*)g_h[pin ^ 1];
            __stcg(&hout[(col >> 1) * 64 + b_g * 2 + (col & 1)], hval);
            ost[b_g * 4 + hu_g] = hval;
        }
        __syncthreads();   // h + ost stores done CTA-wide

        if (t < TSTEPS - 1) {
            if (tid == 0) {
                // Arrive: group counter (acq_rel); last-in-group bumps root (release).
                unsigned old;
                asm volatile("atom.acq_rel.gpu.global.add.u32 %0, [%1], 1;"
                             : "=r"(old) : "l"(grpp) : "memory");
                if (old == 16u * (unsigned)(t + 1) - 1u) {
                    asm volatile("red.release.gpu.global.add.u32 [%0], 1;"
                                 :: "l"(rootp) : "memory");
                }
            }
            // Out store overlaps other CTAs' arrivals.
            if (tid < 32) {
                float4 o4 = *(const float4*)&ost[tid * 4];
                *(float4*)&out[(size_t)t * (BATCH * HDIM) + (size_t)tid * HDIM + cta * 4] = o4;
            }
            if (tid == 0) {
                unsigned target = 8u * (unsigned)(t + 1);
                unsigned v;
                do {
                    asm volatile("ld.acquire.gpu.global.u32 %0, [%1];"
                                 : "=r"(v) : "l"(rootp) : "memory");
                } while (v < target);
            }
            __syncthreads();
        } else {
            if (tid < 32) {
                float4 o4 = *(const float4*)&ost[tid * 4];
                *(float4*)&out[(size_t)t * (BATCH * HDIM) + (size_t)tid * HDIM + cta * 4] = o4;
            }
        }
    }
}

// ---------------------------------------------------------------------------
extern "C" void kernel_launch(void* const* d_in, const int* in_sizes, int n_in,
                              void* d_out, int out_size) {
    const float* emb = (const float*)d_in[0];
    const float* wxi = (const float*)d_in[1];
    const float* whi = (const float*)d_in[2];
    const float* bi  = (const float*)d_in[3];
    const float* wxf = (const float*)d_in[4];
    const float* whf = (const float*)d_in[5];
    const float* bf  = (const float*)d_in[6];
    const float* wxg = (const float*)d_in[7];
    const float* whg = (const float*)d_in[8];
    const float* bg  = (const float*)d_in[9];
    const float* wxo = (const float*)d_in[10];
    const float* who = (const float*)d_in[11];
    const float* bo  = (const float*)d_in[12];
    float* out = (float*)d_out;

    cudaFuncSetAttribute(k_xproj, cudaFuncAttributeMaxDynamicSharedMemorySize, 98304);
    cudaFuncSetAttribute(k_rec,   cudaFuncAttributeMaxDynamicSharedMemorySize, 102400);

    k_xproj<<<dim3(16, TSTEPS), 256, 98304>>>(emb, wxi, wxf, wxg, wxo, bi, bf, bg, bo);
    k_init<<<128, 256>>>();
    // smem floats: whs 8192 | ost 128 | sgate 512 | red 16384  -> 100864 B
    k_rec<<<NCTA, 512, 100864>>>(whi, whf, whg, who, out);
}